// round 1
// baseline (speedup 1.0000x reference)
#include <cuda_runtime.h>

// Problem shapes (fixed by the dataset).
#define BB 2
#define TT 2048
#define DD 1024
#define HH 16
#define DKK 64
#define MTOT (BB*TT)   // 4096 rows

// Scratch (device globals: allocation-free per harness rules).
__device__ float g_Q[BB*TT*DD];    // (B*T, D) == (B,T,H,DK)
__device__ float g_K[BB*TT*DKK];   // (B*T, DK)
__device__ float g_V[BB*TT*DKK];   // (B*T, DK)
__device__ float g_Y[BB*TT*DD];    // attention output before Wo

// ---------------------------------------------------------------------------
// SGEMM: C[M,N] = A[M,K] @ B[K,N], row-major, M%128==0, N%64==0, K%16==0.
// BM=128, BN=64, BK=16, 256 threads, 8x4 micro-tile per thread.
// ---------------------------------------------------------------------------
__global__ __launch_bounds__(256) void sgemm128x64(
    const float* __restrict__ A, const float* __restrict__ Bm,
    float* __restrict__ C, int M, int N, int K)
{
    __shared__ __align__(16) float As[16 * 128];   // As[k][m] (transposed)
    __shared__ __align__(16) float Bs[16 * 64];    // Bs[k][n]

    const int tid = threadIdx.x;
    const int tx = tid & 15;        // column group (n = tx*4)
    const int ty = tid >> 4;        // row group    (m = ty*8)
    const int m0 = blockIdx.y * 128;
    const int n0 = blockIdx.x * 64;

    float acc[8][4];
#pragma unroll
    for (int i = 0; i < 8; i++)
#pragma unroll
        for (int j = 0; j < 4; j++) acc[i][j] = 0.f;

    const int a_row = tid >> 1;          // 0..127
    const int a_k   = (tid & 1) * 8;     // 0 or 8
    const int b_row = tid >> 4;          // 0..15
    const int b_c   = (tid & 15) * 4;    // 0..60

    for (int kt = 0; kt < K; kt += 16) {
        // Load A tile (128x16), store transposed As[k][m]
        const float* ap = A + (size_t)(m0 + a_row) * K + kt + a_k;
        float4 a0 = *(const float4*)ap;
        float4 a1 = *(const float4*)(ap + 4);
        As[(a_k + 0) * 128 + a_row] = a0.x;
        As[(a_k + 1) * 128 + a_row] = a0.y;
        As[(a_k + 2) * 128 + a_row] = a0.z;
        As[(a_k + 3) * 128 + a_row] = a0.w;
        As[(a_k + 4) * 128 + a_row] = a1.x;
        As[(a_k + 5) * 128 + a_row] = a1.y;
        As[(a_k + 6) * 128 + a_row] = a1.z;
        As[(a_k + 7) * 128 + a_row] = a1.w;
        // Load B tile (16x64)
        const float* bp = Bm + (size_t)(kt + b_row) * N + n0 + b_c;
        *(float4*)(Bs + b_row * 64 + b_c) = *(const float4*)bp;
        __syncthreads();

#pragma unroll
        for (int kk = 0; kk < 16; kk++) {
            float4 A0 = *(const float4*)(As + kk * 128 + ty * 8);
            float4 A1 = *(const float4*)(As + kk * 128 + ty * 8 + 4);
            float4 Bv = *(const float4*)(Bs + kk * 64 + tx * 4);
            float ar[8] = {A0.x, A0.y, A0.z, A0.w, A1.x, A1.y, A1.z, A1.w};
            float br[4] = {Bv.x, Bv.y, Bv.z, Bv.w};
#pragma unroll
            for (int i = 0; i < 8; i++)
#pragma unroll
                for (int j = 0; j < 4; j++)
                    acc[i][j] = fmaf(ar[i], br[j], acc[i][j]);
        }
        __syncthreads();
    }

#pragma unroll
    for (int i = 0; i < 8; i++) {
        float4 r = make_float4(acc[i][0], acc[i][1], acc[i][2], acc[i][3]);
        *(float4*)(C + (size_t)(m0 + ty * 8 + i) * N + n0 + tx * 4) = r;
    }
}

// ---------------------------------------------------------------------------
// Flash attention (fp32, causal, multi-query: single K/V head shared by all
// 16 query heads). Grid (T/64, H, B), 256 threads, 64x64 Q/K tiles.
//   Qt[d][i], Kt[d][j]  (d-major -> conflict-free float4 reads in S loop)
//   Vs[j][d]            (conflict-free float4 reads in PV loop)
//   Ss[i][j]            (scores / probabilities)
// ---------------------------------------------------------------------------
#define FLASH_SMEM_FLOATS (4 * 4096 + 192)
#define FLASH_SMEM_BYTES (FLASH_SMEM_FLOATS * 4)

__global__ __launch_bounds__(256) void flash_kernel(
    const float* __restrict__ Q, const float* __restrict__ K,
    const float* __restrict__ V, float* __restrict__ Y)
{
    extern __shared__ __align__(16) float sm[];
    float* Qt     = sm;               // [64][64] Qt[d*64 + i]
    float* Kt     = sm + 4096;        // [64][64] Kt[d*64 + j]
    float* Vs     = sm + 8192;        // [64][64] Vs[j*64 + d]
    float* Ss     = sm + 12288;       // [64][64] Ss[i*64 + j]
    float* row_m  = sm + 16384;       // [64] running max
    float* row_l  = sm + 16448;       // [64] running denom
    float* row_sc = sm + 16512;       // [64] rescale factor

    const int tid = threadIdx.x;
    const int tx = tid & 15;          // j/d group = tx*4
    const int ty = tid >> 4;          // i group   = ty*4
    const int h = blockIdx.y;
    const int b = blockIdx.z;
    const int qb = gridDim.x - 1 - blockIdx.x;   // longest blocks first
    const int i0 = qb * 64;

    // Load Q tile, transposed into Qt[d][i].
    {
        const int i  = tid >> 2;             // 0..63
        const int d0 = (tid & 3) * 16;       // 0,16,32,48
        const float* qp = Q + ((size_t)((b * TT + i0 + i) * HH + h)) * DKK + d0;
#pragma unroll
        for (int q = 0; q < 4; q++) {
            float4 v = *(const float4*)(qp + q * 4);
            const int d = d0 + q * 4;
            Qt[(d + 0) * 64 + i] = v.x;
            Qt[(d + 1) * 64 + i] = v.y;
            Qt[(d + 2) * 64 + i] = v.z;
            Qt[(d + 3) * 64 + i] = v.w;
        }
    }
    if (tid < 64) { row_m[tid] = -1e30f; row_l[tid] = 0.f; }

    float o[4][4];
#pragma unroll
    for (int i = 0; i < 4; i++)
#pragma unroll
        for (int j = 0; j < 4; j++) o[i][j] = 0.f;

    const int nIter = qb + 1;  // causal: key blocks j0 <= i0
    for (int it = 0; it < nIter; it++) {
        const int j0 = it * 64;
        __syncthreads();  // Qt/init visible (it=0); Kt/Vs free of prior readers

        // Load K (transposed) and V tiles.
        {
            const int j  = tid >> 2;
            const int d0 = (tid & 3) * 16;
            const float* kp = K + ((size_t)(b * TT + j0 + j)) * DKK + d0;
            const float* vp = V + ((size_t)(b * TT + j0 + j)) * DKK + d0;
#pragma unroll
            for (int q = 0; q < 4; q++) {
                float4 kv = *(const float4*)(kp + q * 4);
                const int d = d0 + q * 4;
                Kt[(d + 0) * 64 + j] = kv.x;
                Kt[(d + 1) * 64 + j] = kv.y;
                Kt[(d + 2) * 64 + j] = kv.z;
                Kt[(d + 3) * 64 + j] = kv.w;
                *(float4*)(Vs + j * 64 + d0 + q * 4) = *(const float4*)(vp + q * 4);
            }
        }
        __syncthreads();

        // S = Q K^T (4x4 per thread), scaled + causal-masked.
        float s[4][4];
#pragma unroll
        for (int i = 0; i < 4; i++)
#pragma unroll
            for (int j = 0; j < 4; j++) s[i][j] = 0.f;

#pragma unroll 8
        for (int d = 0; d < 64; d++) {
            float4 qf = *(const float4*)(Qt + d * 64 + ty * 4);
            float4 kf = *(const float4*)(Kt + d * 64 + tx * 4);
            float qa[4] = {qf.x, qf.y, qf.z, qf.w};
            float ka[4] = {kf.x, kf.y, kf.z, kf.w};
#pragma unroll
            for (int i = 0; i < 4; i++)
#pragma unroll
                for (int j = 0; j < 4; j++)
                    s[i][j] = fmaf(qa[i], ka[j], s[i][j]);
        }
#pragma unroll
        for (int i = 0; i < 4; i++) {
            const int gi = i0 + ty * 4 + i;
#pragma unroll
            for (int j = 0; j < 4; j++) {
                const int gj = j0 + tx * 4 + j;
                s[i][j] = (gj <= gi) ? s[i][j] * 0.125f : -1e30f;
            }
        }
#pragma unroll
        for (int i = 0; i < 4; i++)
            *(float4*)(Ss + (ty * 4 + i) * 64 + tx * 4) =
                make_float4(s[i][0], s[i][1], s[i][2], s[i][3]);
        __syncthreads();

        // Online-softmax row statistics: 4 threads per row.
        {
            const int r = tid >> 2;
            const int p = tid & 3;
            const float4* rp = (const float4*)(Ss + r * 64 + p * 16);
            float4 c0 = rp[0], c1 = rp[1], c2 = rp[2], c3 = rp[3];
            float mx = fmaxf(fmaxf(fmaxf(c0.x, c0.y), fmaxf(c0.z, c0.w)),
                             fmaxf(fmaxf(c1.x, c1.y), fmaxf(c1.z, c1.w)));
            mx = fmaxf(mx, fmaxf(fmaxf(fmaxf(c2.x, c2.y), fmaxf(c2.z, c2.w)),
                                 fmaxf(fmaxf(c3.x, c3.y), fmaxf(c3.z, c3.w))));
            mx = fmaxf(mx, __shfl_xor_sync(0xffffffffu, mx, 1));
            mx = fmaxf(mx, __shfl_xor_sync(0xffffffffu, mx, 2));
            const float m_old = row_m[r];
            const float m_new = fmaxf(m_old, mx);
            float sum = __expf(c0.x - m_new) + __expf(c0.y - m_new)
                      + __expf(c0.z - m_new) + __expf(c0.w - m_new)
                      + __expf(c1.x - m_new) + __expf(c1.y - m_new)
                      + __expf(c1.z - m_new) + __expf(c1.w - m_new)
                      + __expf(c2.x - m_new) + __expf(c2.y - m_new)
                      + __expf(c2.z - m_new) + __expf(c2.w - m_new)
                      + __expf(c3.x - m_new) + __expf(c3.y - m_new)
                      + __expf(c3.z - m_new) + __expf(c3.w - m_new);
            sum += __shfl_xor_sync(0xffffffffu, sum, 1);
            sum += __shfl_xor_sync(0xffffffffu, sum, 2);
            if (p == 0) {
                const float sc = __expf(m_old - m_new);
                row_sc[r] = sc;
                row_m[r]  = m_new;
                row_l[r]  = row_l[r] * sc + sum;
            }
        }
        __syncthreads();

        // P = exp(S - m_new) into Ss; rescale accumulators.
#pragma unroll
        for (int i = 0; i < 4; i++) {
            const int gi = ty * 4 + i;
            const float mn = row_m[gi];
            const float sc = row_sc[gi];
            float4 p4 = make_float4(__expf(s[i][0] - mn), __expf(s[i][1] - mn),
                                    __expf(s[i][2] - mn), __expf(s[i][3] - mn));
            *(float4*)(Ss + gi * 64 + tx * 4) = p4;
#pragma unroll
            for (int d = 0; d < 4; d++) o[i][d] *= sc;
        }
        __syncthreads();

        // O += P @ V (4 rows x 4 d-cols per thread).
#pragma unroll 8
        for (int j = 0; j < 64; j++) {
            float4 vf = *(const float4*)(Vs + j * 64 + tx * 4);
            float va[4] = {vf.x, vf.y, vf.z, vf.w};
            float pr[4];
#pragma unroll
            for (int i = 0; i < 4; i++) pr[i] = Ss[(ty * 4 + i) * 64 + j];
#pragma unroll
            for (int i = 0; i < 4; i++)
#pragma unroll
                for (int d = 0; d < 4; d++)
                    o[i][d] = fmaf(pr[i], va[d], o[i][d]);
        }
    }

    // Epilogue: normalize and write Y.
#pragma unroll
    for (int i = 0; i < 4; i++) {
        const int gi = ty * 4 + i;
        const float invl = 1.f / row_l[gi];
        float4 r = make_float4(o[i][0] * invl, o[i][1] * invl,
                               o[i][2] * invl, o[i][3] * invl);
        *(float4*)(Y + ((size_t)((b * TT + i0 + gi) * HH + h)) * DKK + tx * 4) = r;
    }
}

// ---------------------------------------------------------------------------
extern "C" void kernel_launch(void* const* d_in, const int* in_sizes, int n_in,
                              void* d_out, int out_size)
{
    (void)in_sizes; (void)n_in; (void)out_size;
    const float* x  = (const float*)d_in[0];
    const float* Wq = (const float*)d_in[1];
    const float* Wk = (const float*)d_in[2];
    const float* Wv = (const float*)d_in[3];
    const float* Wo = (const float*)d_in[4];
    float* out = (float*)d_out;

    float *Qp, *Kp, *Vp, *Yp;
    cudaGetSymbolAddress((void**)&Qp, g_Q);
    cudaGetSymbolAddress((void**)&Kp, g_K);
    cudaGetSymbolAddress((void**)&Vp, g_V);
    cudaGetSymbolAddress((void**)&Yp, g_Y);

    // Idempotent, non-stream API: safe under graph capture.
    cudaFuncSetAttribute(flash_kernel,
                         cudaFuncAttributeMaxDynamicSharedMemorySize,
                         FLASH_SMEM_BYTES);

    // Projections: Q = x@Wq, K = x@Wk, V = x@Wv
    sgemm128x64<<<dim3(DD / 64, MTOT / 128), 256>>>(x, Wq, Qp, MTOT, DD, DD);
    sgemm128x64<<<dim3(DKK / 64, MTOT / 128), 256>>>(x, Wk, Kp, MTOT, DKK, DD);
    sgemm128x64<<<dim3(DKK / 64, MTOT / 128), 256>>>(x, Wv, Vp, MTOT, DKK, DD);

    // Causal multi-query flash attention -> Y
    flash_kernel<<<dim3(TT / 64, HH, BB), 256, FLASH_SMEM_BYTES>>>(Qp, Kp, Vp, Yp);

    // Output projection: out = Y @ Wo
    sgemm128x64<<<dim3(DD / 64, MTOT / 128), 256>>>(Yp, Wo, out, MTOT, DD, DD);
}

// round 3
// speedup vs baseline: 1.3874x; 1.3874x over previous
#include <cuda_runtime.h>
#include <cuda_bf16.h>
#include <cstdint>

// Problem shapes (fixed by the dataset).
#define BB 2
#define TT 2048
#define DD 1024
#define HH 16
#define DKK 64
#define MTOT (BB*TT)     // 4096 rows
#define NQKV 1152        // fused projection width: 1024 Q + 64 K + 64 V

// ---------------------------------------------------------------------------
// Device scratch (allocation-free per harness rules).
// ---------------------------------------------------------------------------
__device__ float g_QKV[MTOT * NQKV];      // fused Q|K|V projections (fp32)
__device__ float g_Y[MTOT * DD];          // attention output before Wo
__device__ unsigned short g_xhi[MTOT * DD], g_xlo[MTOT * DD];    // x as bf16 hi/lo
__device__ unsigned short g_Bhi[NQKV * DD], g_Blo[NQKV * DD];    // [Wq;Wk;Wv]^T bf16
__device__ unsigned short g_Yhi[MTOT * DD], g_Ylo[MTOT * DD];    // Y as bf16 hi/lo
__device__ unsigned short g_Wohi[DD * DD], g_Wolo[DD * DD];      // Wo^T bf16

// ---------------------------------------------------------------------------
// Generic-PTX tensor helpers (NO arch-'a' features: work on plain sm_103).
// ---------------------------------------------------------------------------
__device__ __forceinline__ uint32_t smem_u32(const void* p) {
    uint32_t a;
    asm("{ .reg .u64 t; cvta.to.shared.u64 t, %1; cvt.u32.u64 %0, t; }"
        : "=r"(a) : "l"(p));
    return a;
}

__device__ __forceinline__ void ldsm_x4(uint32_t& r0, uint32_t& r1,
                                        uint32_t& r2, uint32_t& r3, uint32_t a) {
    asm volatile("ldmatrix.sync.aligned.m8n8.x4.shared.b16 {%0,%1,%2,%3}, [%4];"
                 : "=r"(r0), "=r"(r1), "=r"(r2), "=r"(r3) : "r"(a));
}

__device__ __forceinline__ void mma_bf16(float* d, const uint32_t* a,
                                         const uint32_t* b) {
    asm volatile(
        "mma.sync.aligned.m16n8k16.row.col.f32.bf16.bf16.f32 "
        "{%0,%1,%2,%3}, {%4,%5,%6,%7}, {%8,%9}, {%0,%1,%2,%3};"
        : "+f"(d[0]), "+f"(d[1]), "+f"(d[2]), "+f"(d[3])
        : "r"(a[0]), "r"(a[1]), "r"(a[2]), "r"(a[3]), "r"(b[0]), "r"(b[1]));
}

__device__ __forceinline__ void cp_async16(uint32_t saddr, const void* g) {
    asm volatile("cp.async.cg.shared.global [%0], [%1], 16;" :: "r"(saddr), "l"(g));
}
#define CP_COMMIT() asm volatile("cp.async.commit_group;" ::: "memory")
#define CP_WAIT(n)  asm volatile("cp.async.wait_group %0;" :: "n"(n) : "memory")

// ---------------------------------------------------------------------------
// Conversion kernels: fp32 -> bf16 hi/lo split.
// ---------------------------------------------------------------------------
__global__ __launch_bounds__(256) void conv_split(
    const float4* __restrict__ a, __nv_bfloat162* __restrict__ hi,
    __nv_bfloat162* __restrict__ lo, int n4)
{
    int i = blockIdx.x * blockDim.x + threadIdx.x;
    if (i >= n4) return;
    float4 v = a[i];
    __nv_bfloat16 h0 = __float2bfloat16(v.x), h1 = __float2bfloat16(v.y);
    __nv_bfloat16 h2 = __float2bfloat16(v.z), h3 = __float2bfloat16(v.w);
    __nv_bfloat16 l0 = __float2bfloat16(v.x - __bfloat162float(h0));
    __nv_bfloat16 l1 = __float2bfloat16(v.y - __bfloat162float(h1));
    __nv_bfloat16 l2 = __float2bfloat16(v.z - __bfloat162float(h2));
    __nv_bfloat16 l3 = __float2bfloat16(v.w - __bfloat162float(h3));
    hi[2*i]   = __halves2bfloat162(h0, h1);
    hi[2*i+1] = __halves2bfloat162(h2, h3);
    lo[2*i]   = __halves2bfloat162(l0, l1);
    lo[2*i+1] = __halves2bfloat162(l2, l3);
}

// Transpose + split: W[K=1024, N] row-major -> out[(n_off+n)*1024 + k] bf16 hi/lo.
__global__ __launch_bounds__(256) void convT_split(
    const float* __restrict__ W, int N,
    __nv_bfloat16* __restrict__ oh, __nv_bfloat16* __restrict__ ol, int n_off)
{
    __shared__ float t[32][33];
    const int k0 = blockIdx.y * 32, n0 = blockIdx.x * 32;
    const int tx = threadIdx.x & 31, ty = threadIdx.x >> 5;  // 32 x 8
#pragma unroll
    for (int j = 0; j < 4; ++j)
        t[ty + 8*j][tx] = W[(size_t)(k0 + ty + 8*j) * N + n0 + tx];
    __syncthreads();
#pragma unroll
    for (int j = 0; j < 4; ++j) {
        float v = t[tx][ty + 8*j];   // = W[k0+tx][n0+ty+8j]
        __nv_bfloat16 h = __float2bfloat16(v);
        __nv_bfloat16 l = __float2bfloat16(v - __bfloat162float(h));
        size_t o = (size_t)(n_off + n0 + ty + 8*j) * 1024 + k0 + tx;
        oh[o] = h; ol[o] = l;
    }
}

// ---------------------------------------------------------------------------
// Split-bf16 tensor-core GEMM via mma.sync (generic PTX, works on sm_103):
//   C[m][n] = sum_k A[m][k]*B[n][k]   (fp32-accurate via hi/lo 3-product split)
// CTA tile 128x128, 8 warps (each 32x64), K-stage 32, cp.async double buffer.
// Smem rows padded to 80B -> ldmatrix conflict-free.
// ---------------------------------------------------------------------------
#define ROWB 80                 // bytes per smem row (32 bf16 + pad)
#define ARR_B (128 * ROWB)      // 10240 B per array
#define STAGE_B (4 * ARR_B)     // Ahi, Alo, Bhi, Blo
#define GEMM_SMEM_BYTES (2 * STAGE_B)

__global__ __launch_bounds__(256) void gemm_split_mma(
    const __nv_bfloat16* __restrict__ Ah, const __nv_bfloat16* __restrict__ Al,
    const __nv_bfloat16* __restrict__ Bh, const __nv_bfloat16* __restrict__ Bl,
    float* __restrict__ C, int Kd, int ldc)
{
    extern __shared__ __align__(16) char smd[];
    const uint32_t sbase = smem_u32(smd);
    const int tid  = threadIdx.x;
    const int lane = tid & 31;
    const int w    = tid >> 5;
    const int m0 = blockIdx.y * 128;
    const int n0 = blockIdx.x * 128;
    const int mw = (w >> 1) * 32;     // warp m-offset in tile
    const int nw = (w & 1) * 64;      // warp n-offset in tile

    const __nv_bfloat16* gsrc[4] = {Ah, Al, Bh, Bl};

    float acc[2][8][4];
#pragma unroll
    for (int mt = 0; mt < 2; ++mt)
#pragma unroll
        for (int n8 = 0; n8 < 8; ++n8)
#pragma unroll
            for (int q = 0; q < 4; ++q) acc[mt][n8][q] = 0.f;

    const int NS = Kd >> 5;   // K-stages of 32

    // --- stage loader: 2048 x 16B chunks, 8 per thread ---
    auto load_stage = [&](int s) {
        const int kt = s << 5;
        const uint32_t sb = sbase + (s & 1) * STAGE_B;
#pragma unroll
        for (int v = 0; v < 8; ++v) {
            int idx = v * 256 + tid;
            int arr = idx >> 9;          // 0..3
            int r   = (idx >> 2) & 127;
            int c   = idx & 3;
            int grow = (arr < 2 ? m0 : n0) + r;
            const __nv_bfloat16* gp = gsrc[arr] + (size_t)grow * Kd + kt + c * 8;
            cp_async16(sb + arr * ARR_B + r * ROWB + c * 16, gp);
        }
    };

    load_stage(0);
    CP_COMMIT();

    for (int s = 0; s < NS; ++s) {
        if (s + 1 < NS) { load_stage(s + 1); CP_COMMIT(); CP_WAIT(1); }
        else            { CP_WAIT(0); }
        __syncthreads();

        const uint32_t sb = sbase + (s & 1) * STAGE_B;
        const uint32_t aHb = sb + (mw + (lane & 15)) * ROWB + (lane >> 4) * 16;
        const uint32_t aLb = aHb + ARR_B;
        const uint32_t bRow = nw + ((lane >> 4) << 3) + (lane & 7);
        const uint32_t bHb = sb + 2 * ARR_B + bRow * ROWB + ((lane >> 3) & 1) * 16;
        const uint32_t bLb = bHb + ARR_B;

#pragma unroll
        for (int kk = 0; kk < 2; ++kk) {
            const uint32_t ko = kk * 32;       // 16 halfs = 32B
            uint32_t ah[2][4], al[2][4];
            ldsm_x4(ah[0][0], ah[0][1], ah[0][2], ah[0][3], aHb + ko);
            ldsm_x4(ah[1][0], ah[1][1], ah[1][2], ah[1][3], aHb + 16 * ROWB + ko);
            ldsm_x4(al[0][0], al[0][1], al[0][2], al[0][3], aLb + ko);
            ldsm_x4(al[1][0], al[1][1], al[1][2], al[1][3], aLb + 16 * ROWB + ko);

            uint32_t bh[8][2];
#pragma unroll
            for (int g = 0; g < 4; ++g)
                ldsm_x4(bh[2*g][0], bh[2*g][1], bh[2*g+1][0], bh[2*g+1][1],
                        bHb + g * 16 * ROWB + ko);
#pragma unroll
            for (int mt = 0; mt < 2; ++mt)
#pragma unroll
                for (int n8 = 0; n8 < 8; ++n8)
                    mma_bf16(acc[mt][n8], ah[mt], bh[n8]);   // hi*hi
#pragma unroll
            for (int mt = 0; mt < 2; ++mt)
#pragma unroll
                for (int n8 = 0; n8 < 8; ++n8)
                    mma_bf16(acc[mt][n8], al[mt], bh[n8]);   // lo*hi

            uint32_t bl[8][2];
#pragma unroll
            for (int g = 0; g < 4; ++g)
                ldsm_x4(bl[2*g][0], bl[2*g][1], bl[2*g+1][0], bl[2*g+1][1],
                        bLb + g * 16 * ROWB + ko);
#pragma unroll
            for (int mt = 0; mt < 2; ++mt)
#pragma unroll
                for (int n8 = 0; n8 < 8; ++n8)
                    mma_bf16(acc[mt][n8], ah[mt], bl[n8]);   // hi*lo
        }
        __syncthreads();
    }

    // Epilogue: fragment layout -> C
#pragma unroll
    for (int mt = 0; mt < 2; ++mt) {
        const int row = m0 + mw + mt * 16 + (lane >> 2);
        float* c0 = C + (size_t)row * ldc + n0 + nw + (lane & 3) * 2;
        float* c1 = C + (size_t)(row + 8) * ldc + n0 + nw + (lane & 3) * 2;
#pragma unroll
        for (int n8 = 0; n8 < 8; ++n8) {
            *(float2*)(c0 + n8 * 8) = make_float2(acc[mt][n8][0], acc[mt][n8][1]);
            *(float2*)(c1 + n8 * 8) = make_float2(acc[mt][n8][2], acc[mt][n8][3]);
        }
    }
}

// ---------------------------------------------------------------------------
// Flash attention (fp32, causal, multi-query). Reads Q/K/V from the fused
// QKV buffer (row stride NQKV=1152: Q at col h*64, K at 1024, V at 1088).
// ---------------------------------------------------------------------------
#define FLASH_SMEM_FLOATS (4 * 4096 + 192)
#define FLASH_SMEM_BYTES (FLASH_SMEM_FLOATS * 4)

__global__ __launch_bounds__(256) void flash_kernel(
    const float* __restrict__ QKV, float* __restrict__ Y)
{
    extern __shared__ __align__(16) float smf[];
    float* Qt     = smf;               // [64][64] Qt[d*64 + i]
    float* Kt     = smf + 4096;        // [64][64] Kt[d*64 + j]
    float* Vs     = smf + 8192;        // [64][64] Vs[j*64 + d]
    float* Ss     = smf + 12288;       // [64][64]
    float* row_m  = smf + 16384;
    float* row_l  = smf + 16448;
    float* row_sc = smf + 16512;

    const int tid = threadIdx.x;
    const int tx = tid & 15;
    const int ty = tid >> 4;
    const int h = blockIdx.y;
    const int b = blockIdx.z;
    const int qb = gridDim.x - 1 - blockIdx.x;
    const int i0 = qb * 64;

    {
        const int i  = tid >> 2;
        const int d0 = (tid & 3) * 16;
        const float* qp = QKV + (size_t)(b * TT + i0 + i) * NQKV + h * DKK + d0;
#pragma unroll
        for (int q = 0; q < 4; q++) {
            float4 v = *(const float4*)(qp + q * 4);
            const int d = d0 + q * 4;
            Qt[(d + 0) * 64 + i] = v.x;
            Qt[(d + 1) * 64 + i] = v.y;
            Qt[(d + 2) * 64 + i] = v.z;
            Qt[(d + 3) * 64 + i] = v.w;
        }
    }
    if (tid < 64) { row_m[tid] = -1e30f; row_l[tid] = 0.f; }

    float o[4][4];
#pragma unroll
    for (int i = 0; i < 4; i++)
#pragma unroll
        for (int j = 0; j < 4; j++) o[i][j] = 0.f;

    const int nIter = qb + 1;
    for (int it = 0; it < nIter; it++) {
        const int j0 = it * 64;
        __syncthreads();
        {
            const int j  = tid >> 2;
            const int d0 = (tid & 3) * 16;
            const float* kp = QKV + (size_t)(b * TT + j0 + j) * NQKV + 1024 + d0;
            const float* vp = QKV + (size_t)(b * TT + j0 + j) * NQKV + 1088 + d0;
#pragma unroll
            for (int q = 0; q < 4; q++) {
                float4 kv = *(const float4*)(kp + q * 4);
                const int d = d0 + q * 4;
                Kt[(d + 0) * 64 + j] = kv.x;
                Kt[(d + 1) * 64 + j] = kv.y;
                Kt[(d + 2) * 64 + j] = kv.z;
                Kt[(d + 3) * 64 + j] = kv.w;
                *(float4*)(Vs + j * 64 + d0 + q * 4) = *(const float4*)(vp + q * 4);
            }
        }
        __syncthreads();

        float s[4][4];
#pragma unroll
        for (int i = 0; i < 4; i++)
#pragma unroll
            for (int j = 0; j < 4; j++) s[i][j] = 0.f;

#pragma unroll 8
        for (int d = 0; d < 64; d++) {
            float4 qf = *(const float4*)(Qt + d * 64 + ty * 4);
            float4 kf = *(const float4*)(Kt + d * 64 + tx * 4);
            float qa[4] = {qf.x, qf.y, qf.z, qf.w};
            float ka[4] = {kf.x, kf.y, kf.z, kf.w};
#pragma unroll
            for (int i = 0; i < 4; i++)
#pragma unroll
                for (int j = 0; j < 4; j++)
                    s[i][j] = fmaf(qa[i], ka[j], s[i][j]);
        }
#pragma unroll
        for (int i = 0; i < 4; i++) {
            const int gi = i0 + ty * 4 + i;
#pragma unroll
            for (int j = 0; j < 4; j++) {
                const int gj = j0 + tx * 4 + j;
                s[i][j] = (gj <= gi) ? s[i][j] * 0.125f : -1e30f;
            }
        }
#pragma unroll
        for (int i = 0; i < 4; i++)
            *(float4*)(Ss + (ty * 4 + i) * 64 + tx * 4) =
                make_float4(s[i][0], s[i][1], s[i][2], s[i][3]);
        __syncthreads();

        {
            const int r = tid >> 2;
            const int p = tid & 3;
            const float4* rp = (const float4*)(Ss + r * 64 + p * 16);
            float4 c0 = rp[0], c1 = rp[1], c2 = rp[2], c3 = rp[3];
            float mx = fmaxf(fmaxf(fmaxf(c0.x, c0.y), fmaxf(c0.z, c0.w)),
                             fmaxf(fmaxf(c1.x, c1.y), fmaxf(c1.z, c1.w)));
            mx = fmaxf(mx, fmaxf(fmaxf(fmaxf(c2.x, c2.y), fmaxf(c2.z, c2.w)),
                                 fmaxf(fmaxf(c3.x, c3.y), fmaxf(c3.z, c3.w))));
            mx = fmaxf(mx, __shfl_xor_sync(0xffffffffu, mx, 1));
            mx = fmaxf(mx, __shfl_xor_sync(0xffffffffu, mx, 2));
            const float m_old = row_m[r];
            const float m_new = fmaxf(m_old, mx);
            float sum = __expf(c0.x - m_new) + __expf(c0.y - m_new)
                      + __expf(c0.z - m_new) + __expf(c0.w - m_new)
                      + __expf(c1.x - m_new) + __expf(c1.y - m_new)
                      + __expf(c1.z - m_new) + __expf(c1.w - m_new)
                      + __expf(c2.x - m_new) + __expf(c2.y - m_new)
                      + __expf(c2.z - m_new) + __expf(c2.w - m_new)
                      + __expf(c3.x - m_new) + __expf(c3.y - m_new)
                      + __expf(c3.z - m_new) + __expf(c3.w - m_new);
            sum += __shfl_xor_sync(0xffffffffu, sum, 1);
            sum += __shfl_xor_sync(0xffffffffu, sum, 2);
            if (p == 0) {
                const float sc = __expf(m_old - m_new);
                row_sc[r] = sc;
                row_m[r]  = m_new;
                row_l[r]  = row_l[r] * sc + sum;
            }
        }
        __syncthreads();

#pragma unroll
        for (int i = 0; i < 4; i++) {
            const int gi = ty * 4 + i;
            const float mn = row_m[gi];
            const float sc = row_sc[gi];
            float4 p4 = make_float4(__expf(s[i][0] - mn), __expf(s[i][1] - mn),
                                    __expf(s[i][2] - mn), __expf(s[i][3] - mn));
            *(float4*)(Ss + gi * 64 + tx * 4) = p4;
#pragma unroll
            for (int d = 0; d < 4; d++) o[i][d] *= sc;
        }
        __syncthreads();

#pragma unroll 8
        for (int j = 0; j < 64; j++) {
            float4 vf = *(const float4*)(Vs + j * 64 + tx * 4);
            float va[4] = {vf.x, vf.y, vf.z, vf.w};
            float pr[4];
#pragma unroll
            for (int i = 0; i < 4; i++) pr[i] = Ss[(ty * 4 + i) * 64 + j];
#pragma unroll
            for (int i = 0; i < 4; i++)
#pragma unroll
                for (int d = 0; d < 4; d++)
                    o[i][d] = fmaf(pr[i], va[d], o[i][d]);
        }
    }

#pragma unroll
    for (int i = 0; i < 4; i++) {
        const int gi = ty * 4 + i;
        const float invl = 1.f / row_l[gi];
        float4 r = make_float4(o[i][0] * invl, o[i][1] * invl,
                               o[i][2] * invl, o[i][3] * invl);
        *(float4*)(Y + ((size_t)((b * TT + i0 + gi) * HH + h)) * DKK + tx * 4) = r;
    }
}

// ---------------------------------------------------------------------------
extern "C" void kernel_launch(void* const* d_in, const int* in_sizes, int n_in,
                              void* d_out, int out_size)
{
    (void)in_sizes; (void)n_in; (void)out_size;
    const float* x  = (const float*)d_in[0];
    const float* Wq = (const float*)d_in[1];
    const float* Wk = (const float*)d_in[2];
    const float* Wv = (const float*)d_in[3];
    const float* Wo = (const float*)d_in[4];
    float* out = (float*)d_out;

    float *QKVp, *Yp;
    unsigned short *xh, *xl, *Bh, *Bl, *Yh, *Yl, *Woh, *Wol;
    cudaGetSymbolAddress((void**)&QKVp, g_QKV);
    cudaGetSymbolAddress((void**)&Yp, g_Y);
    cudaGetSymbolAddress((void**)&xh, g_xhi);
    cudaGetSymbolAddress((void**)&xl, g_xlo);
    cudaGetSymbolAddress((void**)&Bh, g_Bhi);
    cudaGetSymbolAddress((void**)&Bl, g_Blo);
    cudaGetSymbolAddress((void**)&Yh, g_Yhi);
    cudaGetSymbolAddress((void**)&Yl, g_Ylo);
    cudaGetSymbolAddress((void**)&Woh, g_Wohi);
    cudaGetSymbolAddress((void**)&Wol, g_Wolo);

    cudaFuncSetAttribute(flash_kernel,
                         cudaFuncAttributeMaxDynamicSharedMemorySize, FLASH_SMEM_BYTES);
    cudaFuncSetAttribute(gemm_split_mma,
                         cudaFuncAttributeMaxDynamicSharedMemorySize, GEMM_SMEM_BYTES);

    const int n4x = MTOT * DD / 4;

    // 1) Split x -> bf16 hi/lo
    conv_split<<<n4x / 256, 256>>>((const float4*)x,
        (__nv_bfloat162*)xh, (__nv_bfloat162*)xl, n4x);

    // 2) Transpose+split weights into fused B [N=1152, K=1024] (+ Wo^T)
    convT_split<<<dim3(32, 32), 256>>>(Wq, 1024, (__nv_bfloat16*)Bh, (__nv_bfloat16*)Bl, 0);
    convT_split<<<dim3(2, 32),  256>>>(Wk, 64,   (__nv_bfloat16*)Bh, (__nv_bfloat16*)Bl, 1024);
    convT_split<<<dim3(2, 32),  256>>>(Wv, 64,   (__nv_bfloat16*)Bh, (__nv_bfloat16*)Bl, 1088);
    convT_split<<<dim3(32, 32), 256>>>(Wo, 1024, (__nv_bfloat16*)Woh, (__nv_bfloat16*)Wol, 0);

    // 3) Fused QKV projection: QKV[4096, 1152]
    gemm_split_mma<<<dim3(NQKV / 128, MTOT / 128), 256, GEMM_SMEM_BYTES>>>(
        (const __nv_bfloat16*)xh, (const __nv_bfloat16*)xl,
        (const __nv_bfloat16*)Bh, (const __nv_bfloat16*)Bl,
        QKVp, DD, NQKV);

    // 4) Causal multi-query flash attention -> Y
    flash_kernel<<<dim3(TT / 64, HH, BB), 256, FLASH_SMEM_BYTES>>>(QKVp, Yp);

    // 5) Split Y -> bf16 hi/lo
    conv_split<<<n4x / 256, 256>>>((const float4*)Yp,
        (__nv_bfloat162*)Yh, (__nv_bfloat162*)Yl, n4x);

    // 6) Output projection: out = Y @ Wo
    gemm_split_mma<<<dim3(DD / 128, MTOT / 128), 256, GEMM_SMEM_BYTES>>>(
        (const __nv_bfloat16*)Yh, (const __nv_bfloat16*)Yl,
        (const __nv_bfloat16*)Woh, (const __nv_bfloat16*)Wol,
        out, DD, DD);
}

// round 4
// speedup vs baseline: 3.0715x; 2.2139x over previous
#include <cuda_runtime.h>
#include <cuda_bf16.h>
#include <cstdint>

// Problem shapes (fixed by the dataset).
#define BB 2
#define TT 2048
#define DD 1024
#define HH 16
#define DKK 64
#define MTOT (BB*TT)     // 4096 rows
#define NQKV 1152        // fused projection width: 1024 Q + 64 K + 64 V

// ---------------------------------------------------------------------------
// Device scratch (allocation-free per harness rules).
// ---------------------------------------------------------------------------
__device__ float g_QKV[MTOT * NQKV];      // fused Q|K|V projections (fp32)
__device__ float g_Y[MTOT * DD];          // attention output before Wo
__device__ unsigned short g_QKVh[MTOT * NQKV], g_QKVl[MTOT * NQKV]; // QKV bf16 hi/lo
__device__ unsigned short g_xhi[MTOT * DD], g_xlo[MTOT * DD];    // x as bf16 hi/lo
__device__ unsigned short g_Bhi[NQKV * DD], g_Blo[NQKV * DD];    // [Wq;Wk;Wv]^T bf16
__device__ unsigned short g_Yhi[MTOT * DD], g_Ylo[MTOT * DD];    // Y as bf16 hi/lo
__device__ unsigned short g_Wohi[DD * DD], g_Wolo[DD * DD];      // Wo^T bf16

// ---------------------------------------------------------------------------
// Generic-PTX tensor helpers (NO arch-'a' features: work on plain sm_103).
// ---------------------------------------------------------------------------
__device__ __forceinline__ uint32_t smem_u32(const void* p) {
    uint32_t a;
    asm("{ .reg .u64 t; cvta.to.shared.u64 t, %1; cvt.u32.u64 %0, t; }"
        : "=r"(a) : "l"(p));
    return a;
}

__device__ __forceinline__ void ldsm_x4(uint32_t& r0, uint32_t& r1,
                                        uint32_t& r2, uint32_t& r3, uint32_t a) {
    asm volatile("ldmatrix.sync.aligned.m8n8.x4.shared.b16 {%0,%1,%2,%3}, [%4];"
                 : "=r"(r0), "=r"(r1), "=r"(r2), "=r"(r3) : "r"(a));
}
__device__ __forceinline__ void ldsm_x4_t(uint32_t& r0, uint32_t& r1,
                                          uint32_t& r2, uint32_t& r3, uint32_t a) {
    asm volatile("ldmatrix.sync.aligned.m8n8.x4.trans.shared.b16 {%0,%1,%2,%3}, [%4];"
                 : "=r"(r0), "=r"(r1), "=r"(r2), "=r"(r3) : "r"(a));
}

__device__ __forceinline__ void mma_bf16(float* d, const uint32_t* a,
                                         const uint32_t* b) {
    asm volatile(
        "mma.sync.aligned.m16n8k16.row.col.f32.bf16.bf16.f32 "
        "{%0,%1,%2,%3}, {%4,%5,%6,%7}, {%8,%9}, {%0,%1,%2,%3};"
        : "+f"(d[0]), "+f"(d[1]), "+f"(d[2]), "+f"(d[3])
        : "r"(a[0]), "r"(a[1]), "r"(a[2]), "r"(a[3]), "r"(b[0]), "r"(b[1]));
}

__device__ __forceinline__ void cp_async16(uint32_t saddr, const void* g) {
    asm volatile("cp.async.cg.shared.global [%0], [%1], 16;" :: "r"(saddr), "l"(g));
}
#define CP_COMMIT() asm volatile("cp.async.commit_group;" ::: "memory")
#define CP_WAIT(n)  asm volatile("cp.async.wait_group %0;" :: "n"(n) : "memory")

// Split two fp32 into packed bf16x2 hi & lo parts (low half = first element).
__device__ __forceinline__ void split2(float a, float b, uint32_t& hi, uint32_t& lo) {
    __nv_bfloat16 ha = __float2bfloat16(a), hb = __float2bfloat16(b);
    __nv_bfloat16 la = __float2bfloat16(a - __bfloat162float(ha));
    __nv_bfloat16 lb = __float2bfloat16(b - __bfloat162float(hb));
    __nv_bfloat162 H = __halves2bfloat162(ha, hb);
    __nv_bfloat162 L = __halves2bfloat162(la, lb);
    hi = *reinterpret_cast<uint32_t*>(&H);
    lo = *reinterpret_cast<uint32_t*>(&L);
}

// ---------------------------------------------------------------------------
// Conversion kernels: fp32 -> bf16 hi/lo split.
// ---------------------------------------------------------------------------
__global__ __launch_bounds__(256) void conv_split(
    const float4* __restrict__ a, __nv_bfloat162* __restrict__ hi,
    __nv_bfloat162* __restrict__ lo, int n4)
{
    int i = blockIdx.x * blockDim.x + threadIdx.x;
    if (i >= n4) return;
    float4 v = a[i];
    __nv_bfloat16 h0 = __float2bfloat16(v.x), h1 = __float2bfloat16(v.y);
    __nv_bfloat16 h2 = __float2bfloat16(v.z), h3 = __float2bfloat16(v.w);
    __nv_bfloat16 l0 = __float2bfloat16(v.x - __bfloat162float(h0));
    __nv_bfloat16 l1 = __float2bfloat16(v.y - __bfloat162float(h1));
    __nv_bfloat16 l2 = __float2bfloat16(v.z - __bfloat162float(h2));
    __nv_bfloat16 l3 = __float2bfloat16(v.w - __bfloat162float(h3));
    hi[2*i]   = __halves2bfloat162(h0, h1);
    hi[2*i+1] = __halves2bfloat162(h2, h3);
    lo[2*i]   = __halves2bfloat162(l0, l1);
    lo[2*i+1] = __halves2bfloat162(l2, l3);
}

// Transpose + split: W[K=1024, N] row-major -> out[(n_off+n)*1024 + k] bf16 hi/lo.
__global__ __launch_bounds__(256) void convT_split(
    const float* __restrict__ W, int N,
    __nv_bfloat16* __restrict__ oh, __nv_bfloat16* __restrict__ ol, int n_off)
{
    __shared__ float t[32][33];
    const int k0 = blockIdx.y * 32, n0 = blockIdx.x * 32;
    const int tx = threadIdx.x & 31, ty = threadIdx.x >> 5;  // 32 x 8
#pragma unroll
    for (int j = 0; j < 4; ++j)
        t[ty + 8*j][tx] = W[(size_t)(k0 + ty + 8*j) * N + n0 + tx];
    __syncthreads();
#pragma unroll
    for (int j = 0; j < 4; ++j) {
        float v = t[tx][ty + 8*j];   // = W[k0+tx][n0+ty+8j]
        __nv_bfloat16 h = __float2bfloat16(v);
        __nv_bfloat16 l = __float2bfloat16(v - __bfloat162float(h));
        size_t o = (size_t)(n_off + n0 + ty + 8*j) * 1024 + k0 + tx;
        oh[o] = h; ol[o] = l;
    }
}

// ---------------------------------------------------------------------------
// Split-bf16 tensor-core GEMM via mma.sync (proven in R3).
// ---------------------------------------------------------------------------
#define ROWB 80
#define ARR_B (128 * ROWB)
#define STAGE_B (4 * ARR_B)
#define GEMM_SMEM_BYTES (2 * STAGE_B)

__global__ __launch_bounds__(256) void gemm_split_mma(
    const __nv_bfloat16* __restrict__ Ah, const __nv_bfloat16* __restrict__ Al,
    const __nv_bfloat16* __restrict__ Bh, const __nv_bfloat16* __restrict__ Bl,
    float* __restrict__ C, int Kd, int ldc)
{
    extern __shared__ __align__(16) char smd[];
    const uint32_t sbase = smem_u32(smd);
    const int tid  = threadIdx.x;
    const int lane = tid & 31;
    const int w    = tid >> 5;
    const int m0 = blockIdx.y * 128;
    const int n0 = blockIdx.x * 128;
    const int mw = (w >> 1) * 32;
    const int nw = (w & 1) * 64;

    const __nv_bfloat16* gsrc[4] = {Ah, Al, Bh, Bl};

    float acc[2][8][4];
#pragma unroll
    for (int mt = 0; mt < 2; ++mt)
#pragma unroll
        for (int n8 = 0; n8 < 8; ++n8)
#pragma unroll
            for (int q = 0; q < 4; ++q) acc[mt][n8][q] = 0.f;

    const int NS = Kd >> 5;

    auto load_stage = [&](int s) {
        const int kt = s << 5;
        const uint32_t sb = sbase + (s & 1) * STAGE_B;
#pragma unroll
        for (int v = 0; v < 8; ++v) {
            int idx = v * 256 + tid;
            int arr = idx >> 9;
            int r   = (idx >> 2) & 127;
            int c   = idx & 3;
            int grow = (arr < 2 ? m0 : n0) + r;
            const __nv_bfloat16* gp = gsrc[arr] + (size_t)grow * Kd + kt + c * 8;
            cp_async16(sb + arr * ARR_B + r * ROWB + c * 16, gp);
        }
    };

    load_stage(0);
    CP_COMMIT();

    for (int s = 0; s < NS; ++s) {
        if (s + 1 < NS) { load_stage(s + 1); CP_COMMIT(); CP_WAIT(1); }
        else            { CP_WAIT(0); }
        __syncthreads();

        const uint32_t sb = sbase + (s & 1) * STAGE_B;
        const uint32_t aHb = sb + (mw + (lane & 15)) * ROWB + (lane >> 4) * 16;
        const uint32_t aLb = aHb + ARR_B;
        const uint32_t bRow = nw + ((lane >> 4) << 3) + (lane & 7);
        const uint32_t bHb = sb + 2 * ARR_B + bRow * ROWB + ((lane >> 3) & 1) * 16;
        const uint32_t bLb = bHb + ARR_B;

#pragma unroll
        for (int kk = 0; kk < 2; ++kk) {
            const uint32_t ko = kk * 32;
            uint32_t ah[2][4], al[2][4];
            ldsm_x4(ah[0][0], ah[0][1], ah[0][2], ah[0][3], aHb + ko);
            ldsm_x4(ah[1][0], ah[1][1], ah[1][2], ah[1][3], aHb + 16 * ROWB + ko);
            ldsm_x4(al[0][0], al[0][1], al[0][2], al[0][3], aLb + ko);
            ldsm_x4(al[1][0], al[1][1], al[1][2], al[1][3], aLb + 16 * ROWB + ko);

            uint32_t bh[8][2];
#pragma unroll
            for (int g = 0; g < 4; ++g)
                ldsm_x4(bh[2*g][0], bh[2*g][1], bh[2*g+1][0], bh[2*g+1][1],
                        bHb + g * 16 * ROWB + ko);
#pragma unroll
            for (int mt = 0; mt < 2; ++mt)
#pragma unroll
                for (int n8 = 0; n8 < 8; ++n8)
                    mma_bf16(acc[mt][n8], ah[mt], bh[n8]);
#pragma unroll
            for (int mt = 0; mt < 2; ++mt)
#pragma unroll
                for (int n8 = 0; n8 < 8; ++n8)
                    mma_bf16(acc[mt][n8], al[mt], bh[n8]);

            uint32_t bl[8][2];
#pragma unroll
            for (int g = 0; g < 4; ++g)
                ldsm_x4(bl[2*g][0], bl[2*g][1], bl[2*g+1][0], bl[2*g+1][1],
                        bLb + g * 16 * ROWB + ko);
#pragma unroll
            for (int mt = 0; mt < 2; ++mt)
#pragma unroll
                for (int n8 = 0; n8 < 8; ++n8)
                    mma_bf16(acc[mt][n8], ah[mt], bl[n8]);
        }
        __syncthreads();
    }

#pragma unroll
    for (int mt = 0; mt < 2; ++mt) {
        const int row = m0 + mw + mt * 16 + (lane >> 2);
        float* c0 = C + (size_t)row * ldc + n0 + nw + (lane & 3) * 2;
        float* c1 = C + (size_t)(row + 8) * ldc + n0 + nw + (lane & 3) * 2;
#pragma unroll
        for (int n8 = 0; n8 < 8; ++n8) {
            *(float2*)(c0 + n8 * 8) = make_float2(acc[mt][n8][0], acc[mt][n8][1]);
            *(float2*)(c1 + n8 * 8) = make_float2(acc[mt][n8][2], acc[mt][n8][3]);
        }
    }
}

// ---------------------------------------------------------------------------
// Tensor-core flash attention (causal, multi-query, split-bf16 precision).
// Q tile 128x64 per CTA, 8 warps x 16 rows; K/V tiles 64x64 double-buffered.
// Softmax entirely register-resident (per-warp rows, lane-quad shfl stats).
// ---------------------------------------------------------------------------
#define FT_ROWB 144                 // 64 bf16 = 128B data + 16B pad
#define FT_ARR  (64 * FT_ROWB)      // 9216 B
#define FT_STG  (4 * FT_ARR)        // Kh, Kl, Vh, Vl = 36864 B
#define FT_SMEM (2 * FT_STG)        // 73728 B

__global__ __launch_bounds__(256) void flash_tc(
    const __nv_bfloat16* __restrict__ QKVh,
    const __nv_bfloat16* __restrict__ QKVl,
    float* __restrict__ Y)
{
    extern __shared__ __align__(16) char smd[];
    const uint32_t sbase = smem_u32(smd);
    const int tid = threadIdx.x, lane = tid & 31, wid = tid >> 5;
    const int h = blockIdx.y, b = blockIdx.z;
    const int qb = (int)gridDim.x - 1 - (int)blockIdx.x;   // longest first
    const int i0 = qb * 128;
    const int g = lane >> 2, qd = lane & 3;

    // --- Q fragments (hi/lo), loaded once: [kstep][4 regs] ---
    uint32_t qh[4][4], ql[4][4];
    {
        const int r0 = i0 + wid * 16 + g;
        const size_t b0 = (size_t)(b * TT + r0) * NQKV + h * 64;
        const size_t b1 = b0 + (size_t)8 * NQKV;
#pragma unroll
        for (int t = 0; t < 4; ++t) {
            const int c = t * 16 + qd * 2;
            qh[t][0] = *(const uint32_t*)(QKVh + b0 + c);
            qh[t][1] = *(const uint32_t*)(QKVh + b1 + c);
            qh[t][2] = *(const uint32_t*)(QKVh + b0 + c + 8);
            qh[t][3] = *(const uint32_t*)(QKVh + b1 + c + 8);
            ql[t][0] = *(const uint32_t*)(QKVl + b0 + c);
            ql[t][1] = *(const uint32_t*)(QKVl + b1 + c);
            ql[t][2] = *(const uint32_t*)(QKVl + b0 + c + 8);
            ql[t][3] = *(const uint32_t*)(QKVl + b1 + c + 8);
        }
    }

    float o[8][4];
#pragma unroll
    for (int n8 = 0; n8 < 8; ++n8)
#pragma unroll
        for (int c = 0; c < 4; ++c) o[n8][c] = 0.f;
    float m0 = -1e30f, m1 = -1e30f, l0 = 0.f, l1 = 0.f;

    // --- K/V stage loader (hi/lo, 2048 x 16B chunks, 8 per thread) ---
    auto load_kv = [&](int it) {
        const int j0 = it * 64;
        const uint32_t sb = sbase + (it & 1) * FT_STG;
#pragma unroll
        for (int v = 0; v < 8; ++v) {
            int idx = v * 256 + tid;
            int arr = idx >> 9, r = (idx >> 3) & 63, c = idx & 7;
            const __nv_bfloat16* src = (arr & 1) ? QKVl : QKVh;
            int col = (arr < 2 ? 1024 : 1088) + c * 8;
            cp_async16(sb + arr * FT_ARR + r * FT_ROWB + c * 16,
                       src + (size_t)(b * TT + j0 + r) * NQKV + col);
        }
    };

    load_kv(0);
    CP_COMMIT();

    const int nIter = 2 * qb + 2;
    for (int it = 0; it < nIter; ++it) {
        if (it + 1 < nIter) { load_kv(it + 1); CP_COMMIT(); CP_WAIT(1); }
        else                { CP_WAIT(0); }
        __syncthreads();

        const uint32_t sb = sbase + (it & 1) * FT_STG;

        // ---- S = Q K^T (split: qh*kh + ql*kh + qh*kl) ----
        float s[8][4];
#pragma unroll
        for (int n8 = 0; n8 < 8; ++n8)
#pragma unroll
            for (int c = 0; c < 4; ++c) s[n8][c] = 0.f;

        const uint32_t kA = sb + (((lane >> 4) << 3) + (lane & 7)) * FT_ROWB
                          + ((lane >> 3) & 1) * 16;
#pragma unroll
        for (int t = 0; t < 4; ++t) {
            uint32_t kh[8][2];
#pragma unroll
            for (int gg = 0; gg < 4; ++gg)
                ldsm_x4(kh[2*gg][0], kh[2*gg][1], kh[2*gg+1][0], kh[2*gg+1][1],
                        kA + gg * 16 * FT_ROWB + t * 32);
#pragma unroll
            for (int n8 = 0; n8 < 8; ++n8) mma_bf16(s[n8], qh[t], kh[n8]);
#pragma unroll
            for (int n8 = 0; n8 < 8; ++n8) mma_bf16(s[n8], ql[t], kh[n8]);
            uint32_t kl[8][2];
#pragma unroll
            for (int gg = 0; gg < 4; ++gg)
                ldsm_x4(kl[2*gg][0], kl[2*gg][1], kl[2*gg+1][0], kl[2*gg+1][1],
                        kA + FT_ARR + gg * 16 * FT_ROWB + t * 32);
#pragma unroll
            for (int n8 = 0; n8 < 8; ++n8) mma_bf16(s[n8], qh[t], kl[n8]);
        }

        // ---- scale + causal mask ----
        const int j0 = it * 64;
        const int r0 = i0 + wid * 16 + g;
        const bool msk = (j0 + 63 > i0 + wid * 16);
#pragma unroll
        for (int n8 = 0; n8 < 8; ++n8) {
#pragma unroll
            for (int c = 0; c < 4; ++c) s[n8][c] *= 0.125f;
            if (msk) {
                const int j = j0 + n8 * 8 + qd * 2;
                if (j     > r0)     s[n8][0] = -1e30f;
                if (j + 1 > r0)     s[n8][1] = -1e30f;
                if (j     > r0 + 8) s[n8][2] = -1e30f;
                if (j + 1 > r0 + 8) s[n8][3] = -1e30f;
            }
        }

        // ---- online softmax (register-resident, lane-quad reduce) ----
        float mx0 = -1e30f, mx1 = -1e30f;
#pragma unroll
        for (int n8 = 0; n8 < 8; ++n8) {
            mx0 = fmaxf(mx0, fmaxf(s[n8][0], s[n8][1]));
            mx1 = fmaxf(mx1, fmaxf(s[n8][2], s[n8][3]));
        }
        mx0 = fmaxf(mx0, __shfl_xor_sync(0xffffffffu, mx0, 1));
        mx0 = fmaxf(mx0, __shfl_xor_sync(0xffffffffu, mx0, 2));
        mx1 = fmaxf(mx1, __shfl_xor_sync(0xffffffffu, mx1, 1));
        mx1 = fmaxf(mx1, __shfl_xor_sync(0xffffffffu, mx1, 2));
        const float mn0 = fmaxf(m0, mx0), mn1 = fmaxf(m1, mx1);
        const float sc0 = __expf(m0 - mn0), sc1 = __expf(m1 - mn1);
        m0 = mn0; m1 = mn1;

        float sum0 = 0.f, sum1 = 0.f;
        uint32_t ph[4][4], pl[4][4];
#pragma unroll
        for (int t = 0; t < 4; ++t) {
            float p00 = __expf(s[2*t][0] - mn0),   p01 = __expf(s[2*t][1] - mn0);
            float p02 = __expf(s[2*t][2] - mn1),   p03 = __expf(s[2*t][3] - mn1);
            float p10 = __expf(s[2*t+1][0] - mn0), p11 = __expf(s[2*t+1][1] - mn0);
            float p12 = __expf(s[2*t+1][2] - mn1), p13 = __expf(s[2*t+1][3] - mn1);
            sum0 += p00 + p01 + p10 + p11;
            sum1 += p02 + p03 + p12 + p13;
            split2(p00, p01, ph[t][0], pl[t][0]);
            split2(p02, p03, ph[t][1], pl[t][1]);
            split2(p10, p11, ph[t][2], pl[t][2]);
            split2(p12, p13, ph[t][3], pl[t][3]);
        }
        sum0 += __shfl_xor_sync(0xffffffffu, sum0, 1);
        sum0 += __shfl_xor_sync(0xffffffffu, sum0, 2);
        sum1 += __shfl_xor_sync(0xffffffffu, sum1, 1);
        sum1 += __shfl_xor_sync(0xffffffffu, sum1, 2);
        l0 = l0 * sc0 + sum0;
        l1 = l1 * sc1 + sum1;
#pragma unroll
        for (int n8 = 0; n8 < 8; ++n8) {
            o[n8][0] *= sc0; o[n8][1] *= sc0;
            o[n8][2] *= sc1; o[n8][3] *= sc1;
        }

        // ---- O += P V (split: ph*vh + pl*vh + ph*vl) ----
        const uint32_t vA = sb + 2 * FT_ARR
                          + ((lane & 7) + ((lane >> 3) & 1) * 8) * FT_ROWB
                          + (lane >> 4) * 16;
#pragma unroll
        for (int t = 0; t < 4; ++t) {
            uint32_t vh[8][2];
#pragma unroll
            for (int dg = 0; dg < 4; ++dg)
                ldsm_x4_t(vh[2*dg][0], vh[2*dg][1], vh[2*dg+1][0], vh[2*dg+1][1],
                          vA + t * 16 * FT_ROWB + dg * 32);
#pragma unroll
            for (int n8 = 0; n8 < 8; ++n8) mma_bf16(o[n8], ph[t], vh[n8]);
#pragma unroll
            for (int n8 = 0; n8 < 8; ++n8) mma_bf16(o[n8], pl[t], vh[n8]);
            uint32_t vl[8][2];
#pragma unroll
            for (int dg = 0; dg < 4; ++dg)
                ldsm_x4_t(vl[2*dg][0], vl[2*dg][1], vl[2*dg+1][0], vl[2*dg+1][1],
                          vA + FT_ARR + t * 16 * FT_ROWB + dg * 32);
#pragma unroll
            for (int n8 = 0; n8 < 8; ++n8) mma_bf16(o[n8], ph[t], vl[n8]);
        }
        __syncthreads();
    }

    // ---- epilogue: normalize and write Y ----
    const float inv0 = 1.f / l0, inv1 = 1.f / l1;
    const int r0 = i0 + wid * 16 + g;
    float* y0 = Y + (size_t)(b * TT + r0) * DD + h * 64 + qd * 2;
    float* y1 = y0 + (size_t)8 * DD;
#pragma unroll
    for (int n8 = 0; n8 < 8; ++n8) {
        *(float2*)(y0 + n8 * 8) = make_float2(o[n8][0] * inv0, o[n8][1] * inv0);
        *(float2*)(y1 + n8 * 8) = make_float2(o[n8][2] * inv1, o[n8][3] * inv1);
    }
}

// ---------------------------------------------------------------------------
extern "C" void kernel_launch(void* const* d_in, const int* in_sizes, int n_in,
                              void* d_out, int out_size)
{
    (void)in_sizes; (void)n_in; (void)out_size;
    const float* x  = (const float*)d_in[0];
    const float* Wq = (const float*)d_in[1];
    const float* Wk = (const float*)d_in[2];
    const float* Wv = (const float*)d_in[3];
    const float* Wo = (const float*)d_in[4];
    float* out = (float*)d_out;

    float *QKVp, *Yp;
    unsigned short *qkvh, *qkvl, *xh, *xl, *Bh, *Bl, *Yh, *Yl, *Woh, *Wol;
    cudaGetSymbolAddress((void**)&QKVp, g_QKV);
    cudaGetSymbolAddress((void**)&Yp, g_Y);
    cudaGetSymbolAddress((void**)&qkvh, g_QKVh);
    cudaGetSymbolAddress((void**)&qkvl, g_QKVl);
    cudaGetSymbolAddress((void**)&xh, g_xhi);
    cudaGetSymbolAddress((void**)&xl, g_xlo);
    cudaGetSymbolAddress((void**)&Bh, g_Bhi);
    cudaGetSymbolAddress((void**)&Bl, g_Blo);
    cudaGetSymbolAddress((void**)&Yh, g_Yhi);
    cudaGetSymbolAddress((void**)&Yl, g_Ylo);
    cudaGetSymbolAddress((void**)&Woh, g_Wohi);
    cudaGetSymbolAddress((void**)&Wol, g_Wolo);

    cudaFuncSetAttribute(gemm_split_mma,
                         cudaFuncAttributeMaxDynamicSharedMemorySize, GEMM_SMEM_BYTES);
    cudaFuncSetAttribute(flash_tc,
                         cudaFuncAttributeMaxDynamicSharedMemorySize, FT_SMEM);

    const int n4x = MTOT * DD / 4;
    const int n4q = MTOT * NQKV / 4;

    // 1) Split x -> bf16 hi/lo
    conv_split<<<n4x / 256, 256>>>((const float4*)x,
        (__nv_bfloat162*)xh, (__nv_bfloat162*)xl, n4x);

    // 2) Transpose+split weights into fused B [N=1152, K=1024] (+ Wo^T)
    convT_split<<<dim3(32, 32), 256>>>(Wq, 1024, (__nv_bfloat16*)Bh, (__nv_bfloat16*)Bl, 0);
    convT_split<<<dim3(2, 32),  256>>>(Wk, 64,   (__nv_bfloat16*)Bh, (__nv_bfloat16*)Bl, 1024);
    convT_split<<<dim3(2, 32),  256>>>(Wv, 64,   (__nv_bfloat16*)Bh, (__nv_bfloat16*)Bl, 1088);
    convT_split<<<dim3(32, 32), 256>>>(Wo, 1024, (__nv_bfloat16*)Woh, (__nv_bfloat16*)Wol, 0);

    // 3) Fused QKV projection: QKV[4096, 1152]
    gemm_split_mma<<<dim3(NQKV / 128, MTOT / 128), 256, GEMM_SMEM_BYTES>>>(
        (const __nv_bfloat16*)xh, (const __nv_bfloat16*)xl,
        (const __nv_bfloat16*)Bh, (const __nv_bfloat16*)Bl,
        QKVp, DD, NQKV);

    // 4) Split QKV -> bf16 hi/lo (flash inputs)
    conv_split<<<n4q / 256, 256>>>((const float4*)QKVp,
        (__nv_bfloat162*)qkvh, (__nv_bfloat162*)qkvl, n4q);

    // 5) Tensor-core causal multi-query flash attention -> Y
    flash_tc<<<dim3(TT / 128, HH, BB), 256, FT_SMEM>>>(
        (const __nv_bfloat16*)qkvh, (const __nv_bfloat16*)qkvl, Yp);

    // 6) Split Y -> bf16 hi/lo
    conv_split<<<n4x / 256, 256>>>((const float4*)Yp,
        (__nv_bfloat162*)Yh, (__nv_bfloat162*)Yl, n4x);

    // 7) Output projection: out = Y @ Wo
    gemm_split_mma<<<dim3(DD / 128, MTOT / 128), 256, GEMM_SMEM_BYTES>>>(
        (const __nv_bfloat16*)Yh, (const __nv_bfloat16*)Yl,
        (const __nv_bfloat16*)Woh, (const __nv_bfloat16*)Wol,
        out, DD, DD);
}

// round 5
// speedup vs baseline: 3.0896x; 1.0059x over previous
#include <cuda_runtime.h>
#include <cuda_bf16.h>
#include <cstdint>

// Problem shapes (fixed by the dataset).
#define BB 2
#define TT 2048
#define DD 1024
#define HH 16
#define DKK 64
#define MTOT (BB*TT)     // 4096 rows
#define NQKV 1152        // fused projection width: 1024 Q + 64 K + 64 V

// ---------------------------------------------------------------------------
// Device scratch (allocation-free per harness rules).
// ---------------------------------------------------------------------------
__device__ unsigned short g_QKVh[MTOT * NQKV], g_QKVl[MTOT * NQKV]; // QKV bf16 hi/lo
__device__ unsigned short g_xhi[MTOT * DD], g_xlo[MTOT * DD];    // x as bf16 hi/lo
__device__ unsigned short g_Bhi[NQKV * DD], g_Blo[NQKV * DD];    // [Wq;Wk;Wv]^T bf16
__device__ unsigned short g_Yhi[MTOT * DD], g_Ylo[MTOT * DD];    // Y as bf16 hi/lo
__device__ unsigned short g_Wohi[DD * DD], g_Wolo[DD * DD];      // Wo^T bf16

// ---------------------------------------------------------------------------
// Generic-PTX tensor helpers (NO arch-'a' features: work on plain sm_103).
// ---------------------------------------------------------------------------
__device__ __forceinline__ uint32_t smem_u32(const void* p) {
    uint32_t a;
    asm("{ .reg .u64 t; cvta.to.shared.u64 t, %1; cvt.u32.u64 %0, t; }"
        : "=r"(a) : "l"(p));
    return a;
}

__device__ __forceinline__ void ldsm_x4(uint32_t& r0, uint32_t& r1,
                                        uint32_t& r2, uint32_t& r3, uint32_t a) {
    asm volatile("ldmatrix.sync.aligned.m8n8.x4.shared.b16 {%0,%1,%2,%3}, [%4];"
                 : "=r"(r0), "=r"(r1), "=r"(r2), "=r"(r3) : "r"(a));
}
__device__ __forceinline__ void ldsm_x4_t(uint32_t& r0, uint32_t& r1,
                                          uint32_t& r2, uint32_t& r3, uint32_t a) {
    asm volatile("ldmatrix.sync.aligned.m8n8.x4.trans.shared.b16 {%0,%1,%2,%3}, [%4];"
                 : "=r"(r0), "=r"(r1), "=r"(r2), "=r"(r3) : "r"(a));
}

__device__ __forceinline__ void mma_bf16(float* d, const uint32_t* a,
                                         const uint32_t* b) {
    asm volatile(
        "mma.sync.aligned.m16n8k16.row.col.f32.bf16.bf16.f32 "
        "{%0,%1,%2,%3}, {%4,%5,%6,%7}, {%8,%9}, {%0,%1,%2,%3};"
        : "+f"(d[0]), "+f"(d[1]), "+f"(d[2]), "+f"(d[3])
        : "r"(a[0]), "r"(a[1]), "r"(a[2]), "r"(a[3]), "r"(b[0]), "r"(b[1]));
}

__device__ __forceinline__ void cp_async16(uint32_t saddr, const void* g) {
    asm volatile("cp.async.cg.shared.global [%0], [%1], 16;" :: "r"(saddr), "l"(g));
}
#define CP_COMMIT() asm volatile("cp.async.commit_group;" ::: "memory")
#define CP_WAIT(n)  asm volatile("cp.async.wait_group %0;" :: "n"(n) : "memory")

// Split two fp32 into packed bf16x2 hi & lo parts (low half = first element).
__device__ __forceinline__ void split2(float a, float b, uint32_t& hi, uint32_t& lo) {
    __nv_bfloat16 ha = __float2bfloat16(a), hb = __float2bfloat16(b);
    __nv_bfloat16 la = __float2bfloat16(a - __bfloat162float(ha));
    __nv_bfloat16 lb = __float2bfloat16(b - __bfloat162float(hb));
    __nv_bfloat162 H = __halves2bfloat162(ha, hb);
    __nv_bfloat162 L = __halves2bfloat162(la, lb);
    hi = *reinterpret_cast<uint32_t*>(&H);
    lo = *reinterpret_cast<uint32_t*>(&L);
}

// ---------------------------------------------------------------------------
// Conversion kernels: fp32 -> bf16 hi/lo split.
// ---------------------------------------------------------------------------
__global__ __launch_bounds__(256) void conv_split(
    const float4* __restrict__ a, __nv_bfloat162* __restrict__ hi,
    __nv_bfloat162* __restrict__ lo, int n4)
{
    int i = blockIdx.x * blockDim.x + threadIdx.x;
    if (i >= n4) return;
    float4 v = a[i];
    __nv_bfloat16 h0 = __float2bfloat16(v.x), h1 = __float2bfloat16(v.y);
    __nv_bfloat16 h2 = __float2bfloat16(v.z), h3 = __float2bfloat16(v.w);
    __nv_bfloat16 l0 = __float2bfloat16(v.x - __bfloat162float(h0));
    __nv_bfloat16 l1 = __float2bfloat16(v.y - __bfloat162float(h1));
    __nv_bfloat16 l2 = __float2bfloat16(v.z - __bfloat162float(h2));
    __nv_bfloat16 l3 = __float2bfloat16(v.w - __bfloat162float(h3));
    hi[2*i]   = __halves2bfloat162(h0, h1);
    hi[2*i+1] = __halves2bfloat162(h2, h3);
    lo[2*i]   = __halves2bfloat162(l0, l1);
    lo[2*i+1] = __halves2bfloat162(l2, l3);
}

// Transpose + split: W[K=1024, N] row-major -> out[(n_off+n)*1024 + k] bf16 hi/lo.
__global__ __launch_bounds__(256) void convT_split(
    const float* __restrict__ W, int N,
    __nv_bfloat16* __restrict__ oh, __nv_bfloat16* __restrict__ ol, int n_off)
{
    __shared__ float t[32][33];
    const int k0 = blockIdx.y * 32, n0 = blockIdx.x * 32;
    const int tx = threadIdx.x & 31, ty = threadIdx.x >> 5;  // 32 x 8
#pragma unroll
    for (int j = 0; j < 4; ++j)
        t[ty + 8*j][tx] = W[(size_t)(k0 + ty + 8*j) * N + n0 + tx];
    __syncthreads();
#pragma unroll
    for (int j = 0; j < 4; ++j) {
        float v = t[tx][ty + 8*j];   // = W[k0+tx][n0+ty+8j]
        __nv_bfloat16 h = __float2bfloat16(v);
        __nv_bfloat16 l = __float2bfloat16(v - __bfloat162float(h));
        size_t o = (size_t)(n_off + n0 + ty + 8*j) * 1024 + k0 + tx;
        oh[o] = h; ol[o] = l;
    }
}

// ---------------------------------------------------------------------------
// Split-bf16 tensor-core GEMM via mma.sync. CTA tile 128x128, 8 warps
// (each 32x64), K-stage 64, cp.async double buffer, rows padded to 144B.
// SPLIT_OUT=true: emit bf16 hi/lo (fused conv); false: emit fp32.
// ---------------------------------------------------------------------------
#define ROWB 144                 // 64 bf16 = 128B data + 16B pad
#define ARR_B (128 * ROWB)       // 18432 B
#define STAGE_B (4 * ARR_B)      // 73728 B (Ahi, Alo, Bhi, Blo)
#define GEMM_SMEM_BYTES (2 * STAGE_B)   // 147456 B

template<bool SPLIT_OUT>
__global__ __launch_bounds__(256) void gemm_split_mma(
    const __nv_bfloat16* __restrict__ Ah, const __nv_bfloat16* __restrict__ Al,
    const __nv_bfloat16* __restrict__ Bh, const __nv_bfloat16* __restrict__ Bl,
    float* __restrict__ C, __nv_bfloat16* __restrict__ Ch,
    __nv_bfloat16* __restrict__ Cl, int Kd, int ldc)
{
    extern __shared__ __align__(16) char smd[];
    const uint32_t sbase = smem_u32(smd);
    const int tid  = threadIdx.x;
    const int lane = tid & 31;
    const int w    = tid >> 5;
    const int m0 = blockIdx.y * 128;
    const int n0 = blockIdx.x * 128;
    const int mw = (w >> 1) * 32;
    const int nw = (w & 1) * 64;

    const __nv_bfloat16* gsrc[4] = {Ah, Al, Bh, Bl};

    float acc[2][8][4];
#pragma unroll
    for (int mt = 0; mt < 2; ++mt)
#pragma unroll
        for (int n8 = 0; n8 < 8; ++n8)
#pragma unroll
            for (int q = 0; q < 4; ++q) acc[mt][n8][q] = 0.f;

    const int NS = Kd >> 6;   // K-stages of 64

    // --- stage loader: 4096 x 16B chunks, 16 per thread ---
    auto load_stage = [&](int s) {
        const int kt = s << 6;
        const uint32_t sb = sbase + (s & 1) * STAGE_B;
#pragma unroll
        for (int v = 0; v < 16; ++v) {
            int idx = v * 256 + tid;
            int arr = idx >> 10;          // 0..3
            int r   = (idx >> 3) & 127;
            int c   = idx & 7;
            int grow = (arr < 2 ? m0 : n0) + r;
            const __nv_bfloat16* gp = gsrc[arr] + (size_t)grow * Kd + kt + c * 8;
            cp_async16(sb + arr * ARR_B + r * ROWB + c * 16, gp);
        }
    };

    load_stage(0);
    CP_COMMIT();

    for (int s = 0; s < NS; ++s) {
        if (s + 1 < NS) { load_stage(s + 1); CP_COMMIT(); CP_WAIT(1); }
        else            { CP_WAIT(0); }
        __syncthreads();

        const uint32_t sb = sbase + (s & 1) * STAGE_B;
        const uint32_t aHb = sb + (mw + (lane & 15)) * ROWB + (lane >> 4) * 16;
        const uint32_t aLb = aHb + ARR_B;
        const uint32_t bRow = nw + ((lane >> 4) << 3) + (lane & 7);
        const uint32_t bHb = sb + 2 * ARR_B + bRow * ROWB + ((lane >> 3) & 1) * 16;
        const uint32_t bLb = bHb + ARR_B;

#pragma unroll
        for (int t = 0; t < 4; ++t) {
            const uint32_t ko = t * 32;       // 16 halfs = 32B per k16 step
            uint32_t ah[2][4], al[2][4];
            ldsm_x4(ah[0][0], ah[0][1], ah[0][2], ah[0][3], aHb + ko);
            ldsm_x4(ah[1][0], ah[1][1], ah[1][2], ah[1][3], aHb + 16 * ROWB + ko);
            ldsm_x4(al[0][0], al[0][1], al[0][2], al[0][3], aLb + ko);
            ldsm_x4(al[1][0], al[1][1], al[1][2], al[1][3], aLb + 16 * ROWB + ko);

            uint32_t bh[8][2];
#pragma unroll
            for (int g = 0; g < 4; ++g)
                ldsm_x4(bh[2*g][0], bh[2*g][1], bh[2*g+1][0], bh[2*g+1][1],
                        bHb + g * 16 * ROWB + ko);
#pragma unroll
            for (int mt = 0; mt < 2; ++mt)
#pragma unroll
                for (int n8 = 0; n8 < 8; ++n8)
                    mma_bf16(acc[mt][n8], ah[mt], bh[n8]);   // hi*hi
#pragma unroll
            for (int mt = 0; mt < 2; ++mt)
#pragma unroll
                for (int n8 = 0; n8 < 8; ++n8)
                    mma_bf16(acc[mt][n8], al[mt], bh[n8]);   // lo*hi

            uint32_t bl[8][2];
#pragma unroll
            for (int g = 0; g < 4; ++g)
                ldsm_x4(bl[2*g][0], bl[2*g][1], bl[2*g+1][0], bl[2*g+1][1],
                        bLb + g * 16 * ROWB + ko);
#pragma unroll
            for (int mt = 0; mt < 2; ++mt)
#pragma unroll
                for (int n8 = 0; n8 < 8; ++n8)
                    mma_bf16(acc[mt][n8], ah[mt], bl[n8]);   // hi*lo
        }
        __syncthreads();
    }

    // Epilogue
#pragma unroll
    for (int mt = 0; mt < 2; ++mt) {
        const int row = m0 + mw + mt * 16 + (lane >> 2);
        const int col = n0 + nw + (lane & 3) * 2;
        if (SPLIT_OUT) {
            __nv_bfloat16* h0 = Ch + (size_t)row * ldc + col;
            __nv_bfloat16* h1 = Ch + (size_t)(row + 8) * ldc + col;
            __nv_bfloat16* l0 = Cl + (size_t)row * ldc + col;
            __nv_bfloat16* l1 = Cl + (size_t)(row + 8) * ldc + col;
#pragma unroll
            for (int n8 = 0; n8 < 8; ++n8) {
                uint32_t hh, ll;
                split2(acc[mt][n8][0], acc[mt][n8][1], hh, ll);
                *(uint32_t*)(h0 + n8 * 8) = hh;
                *(uint32_t*)(l0 + n8 * 8) = ll;
                split2(acc[mt][n8][2], acc[mt][n8][3], hh, ll);
                *(uint32_t*)(h1 + n8 * 8) = hh;
                *(uint32_t*)(l1 + n8 * 8) = ll;
            }
        } else {
            float* c0 = C + (size_t)row * ldc + col;
            float* c1 = C + (size_t)(row + 8) * ldc + col;
#pragma unroll
            for (int n8 = 0; n8 < 8; ++n8) {
                *(float2*)(c0 + n8 * 8) = make_float2(acc[mt][n8][0], acc[mt][n8][1]);
                *(float2*)(c1 + n8 * 8) = make_float2(acc[mt][n8][2], acc[mt][n8][3]);
            }
        }
    }
}

// ---------------------------------------------------------------------------
// Tensor-core flash attention (causal, multi-query, split-bf16 precision).
// Q tile 128x64 per CTA, 8 warps x 16 rows; K/V tiles 64x64 double-buffered.
// Softmax entirely register-resident. Epilogue emits Y as bf16 hi/lo (fused).
// ---------------------------------------------------------------------------
#define FT_ROWB 144
#define FT_ARR  (64 * FT_ROWB)
#define FT_STG  (4 * FT_ARR)
#define FT_SMEM (2 * FT_STG)

__global__ __launch_bounds__(256) void flash_tc(
    const __nv_bfloat16* __restrict__ QKVh,
    const __nv_bfloat16* __restrict__ QKVl,
    __nv_bfloat16* __restrict__ Yh, __nv_bfloat16* __restrict__ Yl)
{
    extern __shared__ __align__(16) char smd[];
    const uint32_t sbase = smem_u32(smd);
    const int tid = threadIdx.x, lane = tid & 31, wid = tid >> 5;
    const int h = blockIdx.y, b = blockIdx.z;
    const int qb = (int)gridDim.x - 1 - (int)blockIdx.x;   // longest first
    const int i0 = qb * 128;
    const int g = lane >> 2, qd = lane & 3;

    uint32_t qh[4][4], ql[4][4];
    {
        const int r0 = i0 + wid * 16 + g;
        const size_t b0 = (size_t)(b * TT + r0) * NQKV + h * 64;
        const size_t b1 = b0 + (size_t)8 * NQKV;
#pragma unroll
        for (int t = 0; t < 4; ++t) {
            const int c = t * 16 + qd * 2;
            qh[t][0] = *(const uint32_t*)(QKVh + b0 + c);
            qh[t][1] = *(const uint32_t*)(QKVh + b1 + c);
            qh[t][2] = *(const uint32_t*)(QKVh + b0 + c + 8);
            qh[t][3] = *(const uint32_t*)(QKVh + b1 + c + 8);
            ql[t][0] = *(const uint32_t*)(QKVl + b0 + c);
            ql[t][1] = *(const uint32_t*)(QKVl + b1 + c);
            ql[t][2] = *(const uint32_t*)(QKVl + b0 + c + 8);
            ql[t][3] = *(const uint32_t*)(QKVl + b1 + c + 8);
        }
    }

    float o[8][4];
#pragma unroll
    for (int n8 = 0; n8 < 8; ++n8)
#pragma unroll
        for (int c = 0; c < 4; ++c) o[n8][c] = 0.f;
    float m0 = -1e30f, m1 = -1e30f, l0 = 0.f, l1 = 0.f;

    auto load_kv = [&](int it) {
        const int j0 = it * 64;
        const uint32_t sb = sbase + (it & 1) * FT_STG;
#pragma unroll
        for (int v = 0; v < 8; ++v) {
            int idx = v * 256 + tid;
            int arr = idx >> 9, r = (idx >> 3) & 63, c = idx & 7;
            const __nv_bfloat16* src = (arr & 1) ? QKVl : QKVh;
            int col = (arr < 2 ? 1024 : 1088) + c * 8;
            cp_async16(sb + arr * FT_ARR + r * FT_ROWB + c * 16,
                       src + (size_t)(b * TT + j0 + r) * NQKV + col);
        }
    };

    load_kv(0);
    CP_COMMIT();

    const int nIter = 2 * qb + 2;
    for (int it = 0; it < nIter; ++it) {
        if (it + 1 < nIter) { load_kv(it + 1); CP_COMMIT(); CP_WAIT(1); }
        else                { CP_WAIT(0); }
        __syncthreads();

        const uint32_t sb = sbase + (it & 1) * FT_STG;

        float s[8][4];
#pragma unroll
        for (int n8 = 0; n8 < 8; ++n8)
#pragma unroll
            for (int c = 0; c < 4; ++c) s[n8][c] = 0.f;

        const uint32_t kA = sb + (((lane >> 4) << 3) + (lane & 7)) * FT_ROWB
                          + ((lane >> 3) & 1) * 16;
#pragma unroll
        for (int t = 0; t < 4; ++t) {
            uint32_t kh[8][2];
#pragma unroll
            for (int gg = 0; gg < 4; ++gg)
                ldsm_x4(kh[2*gg][0], kh[2*gg][1], kh[2*gg+1][0], kh[2*gg+1][1],
                        kA + gg * 16 * FT_ROWB + t * 32);
#pragma unroll
            for (int n8 = 0; n8 < 8; ++n8) mma_bf16(s[n8], qh[t], kh[n8]);
#pragma unroll
            for (int n8 = 0; n8 < 8; ++n8) mma_bf16(s[n8], ql[t], kh[n8]);
            uint32_t kl[8][2];
#pragma unroll
            for (int gg = 0; gg < 4; ++gg)
                ldsm_x4(kl[2*gg][0], kl[2*gg][1], kl[2*gg+1][0], kl[2*gg+1][1],
                        kA + FT_ARR + gg * 16 * FT_ROWB + t * 32);
#pragma unroll
            for (int n8 = 0; n8 < 8; ++n8) mma_bf16(s[n8], qh[t], kl[n8]);
        }

        const int j0 = it * 64;
        const int r0 = i0 + wid * 16 + g;
        const bool msk = (j0 + 63 > i0 + wid * 16);
#pragma unroll
        for (int n8 = 0; n8 < 8; ++n8) {
#pragma unroll
            for (int c = 0; c < 4; ++c) s[n8][c] *= 0.125f;
            if (msk) {
                const int j = j0 + n8 * 8 + qd * 2;
                if (j     > r0)     s[n8][0] = -1e30f;
                if (j + 1 > r0)     s[n8][1] = -1e30f;
                if (j     > r0 + 8) s[n8][2] = -1e30f;
                if (j + 1 > r0 + 8) s[n8][3] = -1e30f;
            }
        }

        float mx0 = -1e30f, mx1 = -1e30f;
#pragma unroll
        for (int n8 = 0; n8 < 8; ++n8) {
            mx0 = fmaxf(mx0, fmaxf(s[n8][0], s[n8][1]));
            mx1 = fmaxf(mx1, fmaxf(s[n8][2], s[n8][3]));
        }
        mx0 = fmaxf(mx0, __shfl_xor_sync(0xffffffffu, mx0, 1));
        mx0 = fmaxf(mx0, __shfl_xor_sync(0xffffffffu, mx0, 2));
        mx1 = fmaxf(mx1, __shfl_xor_sync(0xffffffffu, mx1, 1));
        mx1 = fmaxf(mx1, __shfl_xor_sync(0xffffffffu, mx1, 2));
        const float mn0 = fmaxf(m0, mx0), mn1 = fmaxf(m1, mx1);
        const float sc0 = __expf(m0 - mn0), sc1 = __expf(m1 - mn1);
        m0 = mn0; m1 = mn1;

        float sum0 = 0.f, sum1 = 0.f;
        uint32_t ph[4][4], pl[4][4];
#pragma unroll
        for (int t = 0; t < 4; ++t) {
            float p00 = __expf(s[2*t][0] - mn0),   p01 = __expf(s[2*t][1] - mn0);
            float p02 = __expf(s[2*t][2] - mn1),   p03 = __expf(s[2*t][3] - mn1);
            float p10 = __expf(s[2*t+1][0] - mn0), p11 = __expf(s[2*t+1][1] - mn0);
            float p12 = __expf(s[2*t+1][2] - mn1), p13 = __expf(s[2*t+1][3] - mn1);
            sum0 += p00 + p01 + p10 + p11;
            sum1 += p02 + p03 + p12 + p13;
            split2(p00, p01, ph[t][0], pl[t][0]);
            split2(p02, p03, ph[t][1], pl[t][1]);
            split2(p10, p11, ph[t][2], pl[t][2]);
            split2(p12, p13, ph[t][3], pl[t][3]);
        }
        sum0 += __shfl_xor_sync(0xffffffffu, sum0, 1);
        sum0 += __shfl_xor_sync(0xffffffffu, sum0, 2);
        sum1 += __shfl_xor_sync(0xffffffffu, sum1, 1);
        sum1 += __shfl_xor_sync(0xffffffffu, sum1, 2);
        l0 = l0 * sc0 + sum0;
        l1 = l1 * sc1 + sum1;
#pragma unroll
        for (int n8 = 0; n8 < 8; ++n8) {
            o[n8][0] *= sc0; o[n8][1] *= sc0;
            o[n8][2] *= sc1; o[n8][3] *= sc1;
        }

        const uint32_t vA = sb + 2 * FT_ARR
                          + ((lane & 7) + ((lane >> 3) & 1) * 8) * FT_ROWB
                          + (lane >> 4) * 16;
#pragma unroll
        for (int t = 0; t < 4; ++t) {
            uint32_t vh[8][2];
#pragma unroll
            for (int dg = 0; dg < 4; ++dg)
                ldsm_x4_t(vh[2*dg][0], vh[2*dg][1], vh[2*dg+1][0], vh[2*dg+1][1],
                          vA + t * 16 * FT_ROWB + dg * 32);
#pragma unroll
            for (int n8 = 0; n8 < 8; ++n8) mma_bf16(o[n8], ph[t], vh[n8]);
#pragma unroll
            for (int n8 = 0; n8 < 8; ++n8) mma_bf16(o[n8], pl[t], vh[n8]);
            uint32_t vl[8][2];
#pragma unroll
            for (int dg = 0; dg < 4; ++dg)
                ldsm_x4_t(vl[2*dg][0], vl[2*dg][1], vl[2*dg+1][0], vl[2*dg+1][1],
                          vA + FT_ARR + t * 16 * FT_ROWB + dg * 32);
#pragma unroll
            for (int n8 = 0; n8 < 8; ++n8) mma_bf16(o[n8], ph[t], vl[n8]);
        }
        __syncthreads();
    }

    // ---- epilogue: normalize and write Y as bf16 hi/lo (fused split) ----
    const float inv0 = 1.f / l0, inv1 = 1.f / l1;
    const int r0 = i0 + wid * 16 + g;
    const size_t off0 = (size_t)(b * TT + r0) * DD + h * 64 + qd * 2;
    const size_t off1 = off0 + (size_t)8 * DD;
#pragma unroll
    for (int n8 = 0; n8 < 8; ++n8) {
        uint32_t hh, ll;
        split2(o[n8][0] * inv0, o[n8][1] * inv0, hh, ll);
        *(uint32_t*)(Yh + off0 + n8 * 8) = hh;
        *(uint32_t*)(Yl + off0 + n8 * 8) = ll;
        split2(o[n8][2] * inv1, o[n8][3] * inv1, hh, ll);
        *(uint32_t*)(Yh + off1 + n8 * 8) = hh;
        *(uint32_t*)(Yl + off1 + n8 * 8) = ll;
    }
}

// ---------------------------------------------------------------------------
extern "C" void kernel_launch(void* const* d_in, const int* in_sizes, int n_in,
                              void* d_out, int out_size)
{
    (void)in_sizes; (void)n_in; (void)out_size;
    const float* x  = (const float*)d_in[0];
    const float* Wq = (const float*)d_in[1];
    const float* Wk = (const float*)d_in[2];
    const float* Wv = (const float*)d_in[3];
    const float* Wo = (const float*)d_in[4];
    float* out = (float*)d_out;

    unsigned short *qkvh, *qkvl, *xh, *xl, *Bh, *Bl, *Yh, *Yl, *Woh, *Wol;
    cudaGetSymbolAddress((void**)&qkvh, g_QKVh);
    cudaGetSymbolAddress((void**)&qkvl, g_QKVl);
    cudaGetSymbolAddress((void**)&xh, g_xhi);
    cudaGetSymbolAddress((void**)&xl, g_xlo);
    cudaGetSymbolAddress((void**)&Bh, g_Bhi);
    cudaGetSymbolAddress((void**)&Bl, g_Blo);
    cudaGetSymbolAddress((void**)&Yh, g_Yhi);
    cudaGetSymbolAddress((void**)&Yl, g_Ylo);
    cudaGetSymbolAddress((void**)&Woh, g_Wohi);
    cudaGetSymbolAddress((void**)&Wol, g_Wolo);

    cudaFuncSetAttribute(gemm_split_mma<true>,
                         cudaFuncAttributeMaxDynamicSharedMemorySize, GEMM_SMEM_BYTES);
    cudaFuncSetAttribute(gemm_split_mma<false>,
                         cudaFuncAttributeMaxDynamicSharedMemorySize, GEMM_SMEM_BYTES);
    cudaFuncSetAttribute(flash_tc,
                         cudaFuncAttributeMaxDynamicSharedMemorySize, FT_SMEM);

    const int n4x = MTOT * DD / 4;

    // 1) Split x -> bf16 hi/lo
    conv_split<<<n4x / 256, 256>>>((const float4*)x,
        (__nv_bfloat162*)xh, (__nv_bfloat162*)xl, n4x);

    // 2) Transpose+split weights into fused B [N=1152, K=1024] (+ Wo^T)
    convT_split<<<dim3(32, 32), 256>>>(Wq, 1024, (__nv_bfloat16*)Bh, (__nv_bfloat16*)Bl, 0);
    convT_split<<<dim3(2, 32),  256>>>(Wk, 64,   (__nv_bfloat16*)Bh, (__nv_bfloat16*)Bl, 1024);
    convT_split<<<dim3(2, 32),  256>>>(Wv, 64,   (__nv_bfloat16*)Bh, (__nv_bfloat16*)Bl, 1088);
    convT_split<<<dim3(32, 32), 256>>>(Wo, 1024, (__nv_bfloat16*)Woh, (__nv_bfloat16*)Wol, 0);

    // 3) Fused QKV projection, epilogue emits bf16 hi/lo directly
    gemm_split_mma<true><<<dim3(NQKV / 128, MTOT / 128), 256, GEMM_SMEM_BYTES>>>(
        (const __nv_bfloat16*)xh, (const __nv_bfloat16*)xl,
        (const __nv_bfloat16*)Bh, (const __nv_bfloat16*)Bl,
        nullptr, (__nv_bfloat16*)qkvh, (__nv_bfloat16*)qkvl, DD, NQKV);

    // 4) Tensor-core causal multi-query flash attention -> Yh/Yl (fused split)
    flash_tc<<<dim3(TT / 128, HH, BB), 256, FT_SMEM>>>(
        (const __nv_bfloat16*)qkvh, (const __nv_bfloat16*)qkvl,
        (__nv_bfloat16*)Yh, (__nv_bfloat16*)Yl);

    // 5) Output projection: out = Y @ Wo (fp32 epilogue)
    gemm_split_mma<false><<<dim3(DD / 128, MTOT / 128), 256, GEMM_SMEM_BYTES>>>(
        (const __nv_bfloat16*)Yh, (const __nv_bfloat16*)Yl,
        (const __nv_bfloat16*)Woh, (const __nv_bfloat16*)Wol,
        out, nullptr, nullptr, DD, DD);
}